// round 4
// baseline (speedup 1.0000x reference)
#include <cuda_runtime.h>
#include <math.h>
#include <stdint.h>

// Problem constants
#define BATCH 2
#define SEQ   2048
#define DIM   1024
#define HEADS 16
#define DKH   64
#define MTOT  (BATCH * SEQ)   // 4096

// Scratch buffers (device globals — no allocation allowed)
__device__ float g_qp[MTOT * DIM];
__device__ float g_kp[MTOT * DIM];
__device__ float g_vp[MTOT * DIM];
__device__ float g_ao[MTOT * DIM];

// ---------------------------------------------------------------------------
// tf32 round-to-nearest conversion (keeps bits in a float container)
// ---------------------------------------------------------------------------
__device__ __forceinline__ float to_tf32(float x) {
    uint32_t u;
    asm("cvt.rna.tf32.f32 %0, %1;" : "=r"(u) : "f"(x));
    return __uint_as_float(u);
}

#define MMA_TF32(c, a0, a1, a2, a3, b0, b1)                                   \
    asm volatile(                                                             \
        "mma.sync.aligned.m16n8k8.row.col.f32.tf32.tf32.f32 "                 \
        "{%0,%1,%2,%3}, {%4,%5,%6,%7}, {%8,%9}, {%0,%1,%2,%3};"               \
        : "+f"((c)[0]), "+f"((c)[1]), "+f"((c)[2]), "+f"((c)[3])              \
        : "r"(__float_as_uint(a0)), "r"(__float_as_uint(a1)),                 \
          "r"(__float_as_uint(a2)), "r"(__float_as_uint(a3)),                 \
          "r"(__float_as_uint(b0)), "r"(__float_as_uint(b1)))

// ---------------------------------------------------------------------------
// tf32 tensor-core GEMM: C[M,N] = A[M,K] @ W[N,K]^T  (both row-major "NT")
// Block tile 128x128, BK=32, 256 threads = 8 warps (2x4), warp tile 64x32.
// Smem columns permuted within each 16-k block: pos(k) = (k&3)*4 + ((k>>2)&3)
// so each mma fragment pair (two k8 groups) is a single float4 load.
// ---------------------------------------------------------------------------
__global__ __launch_bounds__(256) void sgemm_tf32(const float* __restrict__ A,
                                                  const float* __restrict__ W,
                                                  float* __restrict__ C,
                                                  int M, int N, int K) {
    __shared__ float As[128][36];
    __shared__ float Bs[128][36];

    const int tid  = threadIdx.x;
    const int wid  = tid >> 5;
    const int lane = tid & 31;
    const int bm = blockIdx.y * 128;
    const int bn = blockIdx.x * 128;
    const int wm = (wid >> 2) * 64;   // 0 or 64
    const int wn = (wid & 3) * 32;    // 0,32,64,96
    const int lr = lane >> 2;         // 0..7
    const int lc = lane & 3;          // 0..3

    float acc[4][4][4];
#pragma unroll
    for (int i = 0; i < 4; i++)
#pragma unroll
        for (int j = 0; j < 4; j++)
#pragma unroll
            for (int r = 0; r < 4; r++) acc[i][j][r] = 0.f;

    for (int k0 = 0; k0 < K; k0 += 32) {
        // Prefetch GMEM into registers
        float4 ra[4], rb[4];
#pragma unroll
        for (int it = 0; it < 4; it++) {
            int id  = tid + it * 256;   // 0..1023
            int row = id >> 3;          // 0..127
            int seg = id & 7;           // 0..7
            ra[it] = *(const float4*)(A + (size_t)(bm + row) * K + k0 + seg * 4);
            rb[it] = *(const float4*)(W + (size_t)(bn + row) * K + k0 + seg * 4);
        }

        __syncthreads();   // previous iteration done reading smem

        // Store with tf32 conversion + column permutation
#pragma unroll
        for (int it = 0; it < 4; it++) {
            int id  = tid + it * 256;
            int row = id >> 3;
            int seg = id & 7;
            float va[4] = {ra[it].x, ra[it].y, ra[it].z, ra[it].w};
            float vb[4] = {rb[it].x, rb[it].y, rb[it].z, rb[it].w};
#pragma unroll
            for (int j = 0; j < 4; j++) {
                int k = seg * 4 + j;
                int c = k & 15;
                int col = (k & 16) + (c & 3) * 4 + (c >> 2);
                As[row][col] = to_tf32(va[j]);
                Bs[row][col] = to_tf32(vb[j]);
            }
        }
        __syncthreads();

        // Two 16-k blocks, each = two k8 mma groups
#pragma unroll
        for (int blk = 0; blk < 2; blk++) {
            int kb = blk * 16;
            float4 alo[4], ahi[4], bf[4];
#pragma unroll
            for (int i = 0; i < 4; i++) {
                alo[i] = *(const float4*)&As[wm + i * 16 + lr][kb + lc * 4];
                ahi[i] = *(const float4*)&As[wm + i * 16 + 8 + lr][kb + lc * 4];
            }
#pragma unroll
            for (int j = 0; j < 4; j++)
                bf[j] = *(const float4*)&Bs[wn + j * 8 + lr][kb + lc * 4];
#pragma unroll
            for (int i = 0; i < 4; i++)
#pragma unroll
                for (int j = 0; j < 4; j++) {
                    MMA_TF32(acc[i][j], alo[i].x, ahi[i].x, alo[i].y, ahi[i].y,
                             bf[j].x, bf[j].y);
                    MMA_TF32(acc[i][j], alo[i].z, ahi[i].z, alo[i].w, ahi[i].w,
                             bf[j].z, bf[j].w);
                }
        }
    }

    // Epilogue: c0/c1 at (row, col..col+1), c2/c3 at (row+8, ...)
#pragma unroll
    for (int i = 0; i < 4; i++)
#pragma unroll
        for (int j = 0; j < 4; j++) {
            int row = bm + wm + i * 16 + lr;
            int col = bn + wn + j * 8 + lc * 2;
            *(float2*)&C[(size_t)row * N + col] =
                make_float2(acc[i][j][0], acc[i][j][1]);
            *(float2*)&C[(size_t)(row + 8) * N + col] =
                make_float2(acc[i][j][2], acc[i][j][3]);
        }
}

// ---------------------------------------------------------------------------
// Flash attention, register-tiled, with XOR-swizzled transposed tiles.
// Grid: (SEQ/64, HEADS, BATCH). Block: 256 threads as 16x16.
// Transposed Q^T/K^T use physical float4-column  c ^ (d>>2)  — the transpose
// store becomes ~4-way (was 16-way) conflicted; reads stay conflict-free.
// ---------------------------------------------------------------------------
__global__ __launch_bounds__(256) void attn_kernel(const float* __restrict__ Qp,
                                                   const float* __restrict__ Kp,
                                                   const float* __restrict__ Vp,
                                                   const int* __restrict__ mask,
                                                   float* __restrict__ O) {
    __shared__ float Qt[64 * 64];   // Q^T swizzled, pre-scaled by 1/8
    __shared__ float KP[64 * 64];   // K^T swizzled  /  P natural [row][key]
    __shared__ float Vs[64 * 64];   // V natural [key][dk]

    const int tid = threadIdx.x;
    const int q0 = blockIdx.x * 64;
    const int h  = blockIdx.y;
    const int b  = blockIdx.z;
    const int tx = tid & 15;
    const int ty = tid >> 4;

    const size_t base = (size_t)b * SEQ * DIM + (size_t)h * DKH;

    // Load Q tile transposed + swizzled, scaled by 0.125
#pragma unroll
    for (int it = 0; it < 4; it++) {
        int id = tid + it * 256;
        int r  = id >> 4;          // row 0..63
        int d4 = id & 15;          // d-group: covers d = d4*4..d4*4+3, d>>2 == d4
        float4 v = *(const float4*)(Qp + base + (size_t)(q0 + r) * DIM + d4 * 4);
        int cs = ((r >> 2) ^ d4) * 4 + (r & 3);
        Qt[(d4 * 4 + 0) * 64 + cs] = v.x * 0.125f;
        Qt[(d4 * 4 + 1) * 64 + cs] = v.y * 0.125f;
        Qt[(d4 * 4 + 2) * 64 + cs] = v.z * 0.125f;
        Qt[(d4 * 4 + 3) * 64 + cs] = v.w * 0.125f;
    }

    float acc[4][4];
#pragma unroll
    for (int i = 0; i < 4; i++)
#pragma unroll
        for (int j = 0; j < 4; j++) acc[i][j] = 0.f;
    float m[4], l[4];
#pragma unroll
    for (int i = 0; i < 4; i++) { m[i] = -INFINITY; l[i] = 0.f; }

    const int* mbase = mask + (size_t)b * SEQ * SEQ;

    for (int k0 = 0; k0 < SEQ; k0 += 64) {
        __syncthreads();

        // K^T swizzled into KP; V natural into Vs
#pragma unroll
        for (int it = 0; it < 4; it++) {
            int id = tid + it * 256;
            int r  = id >> 4;
            int d4 = id & 15;
            float4 kv = *(const float4*)(Kp + base + (size_t)(k0 + r) * DIM + d4 * 4);
            int cs = ((r >> 2) ^ d4) * 4 + (r & 3);
            KP[(d4 * 4 + 0) * 64 + cs] = kv.x;
            KP[(d4 * 4 + 1) * 64 + cs] = kv.y;
            KP[(d4 * 4 + 2) * 64 + cs] = kv.z;
            KP[(d4 * 4 + 3) * 64 + cs] = kv.w;
            *(float4*)&Vs[r * 64 + d4 * 4] =
                *(const float4*)(Vp + base + (size_t)(k0 + r) * DIM + d4 * 4);
        }

        int4 mv[4];
#pragma unroll
        for (int i = 0; i < 4; i++)
            mv[i] = *(const int4*)(mbase + (size_t)(q0 + ty * 4 + i) * SEQ + k0 + tx * 4);

        __syncthreads();

        // Scores
        float s[4][4];
#pragma unroll
        for (int i = 0; i < 4; i++)
#pragma unroll
            for (int j = 0; j < 4; j++) s[i][j] = 0.f;

#pragma unroll 8
        for (int d = 0; d < 64; d++) {
            int sw = d >> 2;
            float4 qv = *(const float4*)&Qt[d * 64 + ((ty ^ sw) & 15) * 4];
            float4 kv = *(const float4*)&KP[d * 64 + ((tx ^ sw) & 15) * 4];
            float qa[4] = {qv.x, qv.y, qv.z, qv.w};
            float ka[4] = {kv.x, kv.y, kv.z, kv.w};
#pragma unroll
            for (int i = 0; i < 4; i++)
#pragma unroll
                for (int j = 0; j < 4; j++) s[i][j] += qa[i] * ka[j];
        }

        // Mask (value 1e-9 BEFORE softmax, faithful to reference)
        {
            int mm[4][4];
#pragma unroll
            for (int i = 0; i < 4; i++) {
                mm[i][0] = mv[i].x; mm[i][1] = mv[i].y;
                mm[i][2] = mv[i].z; mm[i][3] = mv[i].w;
            }
#pragma unroll
            for (int i = 0; i < 4; i++)
#pragma unroll
                for (int j = 0; j < 4; j++)
                    s[i][j] = (mm[i][j] == 0) ? 1e-9f : s[i][j];
        }

        // Online softmax stats across the 16 tx lanes
        float mn[4], sc[4], ps[4];
#pragma unroll
        for (int i = 0; i < 4; i++) {
            float tm = fmaxf(fmaxf(s[i][0], s[i][1]), fmaxf(s[i][2], s[i][3]));
#pragma unroll
            for (int w = 1; w < 16; w <<= 1)
                tm = fmaxf(tm, __shfl_xor_sync(0xffffffffu, tm, w));
            mn[i] = fmaxf(m[i], tm);
            sc[i] = __expf(m[i] - mn[i]);
            float p0 = __expf(s[i][0] - mn[i]);
            float p1 = __expf(s[i][1] - mn[i]);
            float p2 = __expf(s[i][2] - mn[i]);
            float p3 = __expf(s[i][3] - mn[i]);
            s[i][0] = p0; s[i][1] = p1; s[i][2] = p2; s[i][3] = p3;
            float sum = p0 + p1 + p2 + p3;
#pragma unroll
            for (int w = 1; w < 16; w <<= 1)
                sum += __shfl_xor_sync(0xffffffffu, sum, w);
            ps[i] = sum;
        }

        __syncthreads();   // done reading K^T before P overwrite

#pragma unroll
        for (int i = 0; i < 4; i++)
            *(float4*)&KP[(ty * 4 + i) * 64 + tx * 4] =
                make_float4(s[i][0], s[i][1], s[i][2], s[i][3]);

#pragma unroll
        for (int i = 0; i < 4; i++) {
            l[i] = l[i] * sc[i] + ps[i];
            m[i] = mn[i];
#pragma unroll
            for (int j = 0; j < 4; j++) acc[i][j] *= sc[i];
        }

        __syncthreads();   // P visible

        // AV
#pragma unroll 4
        for (int kc = 0; kc < 16; kc++) {
            float4 pv[4];
#pragma unroll
            for (int i = 0; i < 4; i++)
                pv[i] = *(const float4*)&KP[(ty * 4 + i) * 64 + kc * 4];
#pragma unroll
            for (int jj = 0; jj < 4; jj++) {
                float4 vv = *(const float4*)&Vs[(kc * 4 + jj) * 64 + tx * 4];
                float pj[4] = { ((const float*)&pv[0])[jj], ((const float*)&pv[1])[jj],
                                ((const float*)&pv[2])[jj], ((const float*)&pv[3])[jj] };
#pragma unroll
                for (int i = 0; i < 4; i++) {
                    acc[i][0] += pj[i] * vv.x;
                    acc[i][1] += pj[i] * vv.y;
                    acc[i][2] += pj[i] * vv.z;
                    acc[i][3] += pj[i] * vv.w;
                }
            }
        }
    }

    // Epilogue
#pragma unroll
    for (int i = 0; i < 4; i++) {
        float inv = 1.f / l[i];
        float* op = O + base + (size_t)(q0 + ty * 4 + i) * DIM + tx * 4;
        *(float4*)op = make_float4(acc[i][0] * inv, acc[i][1] * inv,
                                   acc[i][2] * inv, acc[i][3] * inv);
    }
}

// ---------------------------------------------------------------------------
// Launch
// ---------------------------------------------------------------------------
extern "C" void kernel_launch(void* const* d_in, const int* in_sizes, int n_in,
                              void* d_out, int out_size) {
    const float* Q    = (const float*)d_in[0];
    const float* K    = (const float*)d_in[1];
    const float* V    = (const float*)d_in[2];
    const int*   mask = (const int*)d_in[3];
    const float* Wq   = (const float*)d_in[4];
    const float* Wk   = (const float*)d_in[5];
    const float* Wv   = (const float*)d_in[6];
    const float* Wo   = (const float*)d_in[7];
    float* out = (float*)d_out;

    float *qp, *kp, *vp, *ao;
    cudaGetSymbolAddress((void**)&qp, g_qp);
    cudaGetSymbolAddress((void**)&kp, g_kp);
    cudaGetSymbolAddress((void**)&vp, g_vp);
    cudaGetSymbolAddress((void**)&ao, g_ao);

    dim3 gsz(DIM / 128, MTOT / 128);   // (8, 32)
    sgemm_tf32<<<gsz, 256>>>(Q, Wq, qp, MTOT, DIM, DIM);
    sgemm_tf32<<<gsz, 256>>>(K, Wk, kp, MTOT, DIM, DIM);
    sgemm_tf32<<<gsz, 256>>>(V, Wv, vp, MTOT, DIM, DIM);

    dim3 agrid(SEQ / 64, HEADS, BATCH);   // (32, 16, 2)
    attn_kernel<<<agrid, 256>>>(qp, kp, vp, mask, ao);

    sgemm_tf32<<<gsz, 256>>>(ao, Wo, out, MTOT, DIM, DIM);
}

// round 5
// speedup vs baseline: 1.7856x; 1.7856x over previous
#include <cuda_runtime.h>
#include <math.h>
#include <stdint.h>

// Problem constants
#define BATCH 2
#define SEQ   2048
#define DIM   1024
#define HEADS 16
#define DKH   64
#define MTOT  (BATCH * SEQ)   // 4096

// Scratch buffers (device globals — no allocation allowed)
__device__ float g_qp[MTOT * DIM];
__device__ float g_kp[MTOT * DIM];
__device__ float g_vp[MTOT * DIM];
__device__ float g_ao[MTOT * DIM];

// ---------------------------------------------------------------------------
// tf32 helpers
// ---------------------------------------------------------------------------
__device__ __forceinline__ float to_tf32(float x) {
    uint32_t u;
    asm("cvt.rna.tf32.f32 %0, %1;" : "=r"(u) : "f"(x));
    return __uint_as_float(u);
}

#define MMA_TF32(c, a0, a1, a2, a3, b0, b1)                                   \
    asm volatile(                                                             \
        "mma.sync.aligned.m16n8k8.row.col.f32.tf32.tf32.f32 "                 \
        "{%0,%1,%2,%3}, {%4,%5,%6,%7}, {%8,%9}, {%0,%1,%2,%3};"               \
        : "+f"((c)[0]), "+f"((c)[1]), "+f"((c)[2]), "+f"((c)[3])              \
        : "r"(__float_as_uint(a0)), "r"(__float_as_uint(a1)),                 \
          "r"(__float_as_uint(a2)), "r"(__float_as_uint(a3)),                 \
          "r"(__float_as_uint(b0)), "r"(__float_as_uint(b1)))

// ---------------------------------------------------------------------------
// tf32 tensor-core GEMM: C[M,N] = A[M,K] @ W[N,K]^T  (both row-major "NT")
// Block tile 128x128, BK=32, 256 threads = 8 warps (2x4), warp tile 64x32.
// ---------------------------------------------------------------------------
__global__ __launch_bounds__(256) void sgemm_tf32(const float* __restrict__ A,
                                                  const float* __restrict__ W,
                                                  float* __restrict__ C,
                                                  int M, int N, int K) {
    __shared__ float As[128][36];
    __shared__ float Bs[128][36];

    const int tid  = threadIdx.x;
    const int wid  = tid >> 5;
    const int lane = tid & 31;
    const int bm = blockIdx.y * 128;
    const int bn = blockIdx.x * 128;
    const int wm = (wid >> 2) * 64;
    const int wn = (wid & 3) * 32;
    const int lr = lane >> 2;
    const int lc = lane & 3;

    float acc[4][4][4];
#pragma unroll
    for (int i = 0; i < 4; i++)
#pragma unroll
        for (int j = 0; j < 4; j++)
#pragma unroll
            for (int r = 0; r < 4; r++) acc[i][j][r] = 0.f;

    for (int k0 = 0; k0 < K; k0 += 32) {
        float4 ra[4], rb[4];
#pragma unroll
        for (int it = 0; it < 4; it++) {
            int id  = tid + it * 256;
            int row = id >> 3;
            int seg = id & 7;
            ra[it] = *(const float4*)(A + (size_t)(bm + row) * K + k0 + seg * 4);
            rb[it] = *(const float4*)(W + (size_t)(bn + row) * K + k0 + seg * 4);
        }

        __syncthreads();

#pragma unroll
        for (int it = 0; it < 4; it++) {
            int id  = tid + it * 256;
            int row = id >> 3;
            int seg = id & 7;
            float va[4] = {ra[it].x, ra[it].y, ra[it].z, ra[it].w};
            float vb[4] = {rb[it].x, rb[it].y, rb[it].z, rb[it].w};
#pragma unroll
            for (int j = 0; j < 4; j++) {
                int k = seg * 4 + j;
                int c = k & 15;
                int col = (k & 16) + (c & 3) * 4 + (c >> 2);
                As[row][col] = to_tf32(va[j]);
                Bs[row][col] = to_tf32(vb[j]);
            }
        }
        __syncthreads();

#pragma unroll
        for (int blk = 0; blk < 2; blk++) {
            int kb = blk * 16;
            float4 alo[4], ahi[4], bf[4];
#pragma unroll
            for (int i = 0; i < 4; i++) {
                alo[i] = *(const float4*)&As[wm + i * 16 + lr][kb + lc * 4];
                ahi[i] = *(const float4*)&As[wm + i * 16 + 8 + lr][kb + lc * 4];
            }
#pragma unroll
            for (int j = 0; j < 4; j++)
                bf[j] = *(const float4*)&Bs[wn + j * 8 + lr][kb + lc * 4];
#pragma unroll
            for (int i = 0; i < 4; i++)
#pragma unroll
                for (int j = 0; j < 4; j++) {
                    MMA_TF32(acc[i][j], alo[i].x, ahi[i].x, alo[i].y, ahi[i].y,
                             bf[j].x, bf[j].y);
                    MMA_TF32(acc[i][j], alo[i].z, ahi[i].z, alo[i].w, ahi[i].w,
                             bf[j].z, bf[j].w);
                }
        }
    }

#pragma unroll
    for (int i = 0; i < 4; i++)
#pragma unroll
        for (int j = 0; j < 4; j++) {
            int row = bm + wm + i * 16 + lr;
            int col = bn + wn + j * 8 + lc * 2;
            *(float2*)&C[(size_t)row * N + col] =
                make_float2(acc[i][j][0], acc[i][j][1]);
            *(float2*)&C[(size_t)(row + 8) * N + col] =
                make_float2(acc[i][j][2], acc[i][j][3]);
        }
}

// ---------------------------------------------------------------------------
// Flash attention on tf32 tensor cores.
// Grid (SEQ/64, HEADS, BATCH), 128 threads = 4 warps; warp w owns q-rows
// [w*16, w*16+16). Per 64-key tile:
//   S-frag[kb] (16x8 C-frags, kb=0..7) = Qfrag @ Ks^T   (mma m16n8k8)
//   fp32 online softmax on fragments (quad shuffles for row stats)
//   P (tf32) stored into Ks region (warp-local rows), O-frags += P @ Vs
// Ks/Vs natural row-major, stride 72 words: PV B-loads conflict-free,
// QK B-loads 2-way.
// ---------------------------------------------------------------------------
__global__ __launch_bounds__(128) void attn_kernel(const float* __restrict__ Qp,
                                                   const float* __restrict__ Kp,
                                                   const float* __restrict__ Vp,
                                                   const int* __restrict__ mask,
                                                   float* __restrict__ O) {
    __shared__ float Ks[64][72];   // K tile (tf32) / later P tile [qrow][key]
    __shared__ float Vs[64][72];   // V tile (tf32) [key][dk]

    const int tid  = threadIdx.x;
    const int w    = tid >> 5;
    const int lane = tid & 31;
    const int r    = lane >> 2;    // 0..7
    const int c    = lane & 3;     // 0..3
    const int q0   = blockIdx.x * 64;
    const int h    = blockIdx.y;
    const int b    = blockIdx.z;

    const size_t base = (size_t)b * SEQ * DIM + (size_t)h * DKH;
    const int qrow = q0 + w * 16 + r;     // this thread's first q row

    // Preload Q A-fragments for all 8 k-steps (d = 0..63), scaled by 1/8.
    float aq[8][4];
    {
        const float* qr0 = Qp + base + (size_t)qrow * DIM;
        const float* qr8 = qr0 + 8 * DIM;
#pragma unroll
        for (int ks = 0; ks < 8; ks++) {
            aq[ks][0] = to_tf32(qr0[ks * 8 + c]     * 0.125f);
            aq[ks][1] = to_tf32(qr8[ks * 8 + c]     * 0.125f);
            aq[ks][2] = to_tf32(qr0[ks * 8 + c + 4] * 0.125f);
            aq[ks][3] = to_tf32(qr8[ks * 8 + c + 4] * 0.125f);
        }
    }

    float ao[8][4];
#pragma unroll
    for (int kb = 0; kb < 8; kb++)
#pragma unroll
        for (int j = 0; j < 4; j++) ao[kb][j] = 0.f;
    float mst[2] = {-INFINITY, -INFINITY};
    float lst[2] = {0.f, 0.f};

    const int* mrow0 = mask + (size_t)b * SEQ * SEQ + (size_t)qrow * SEQ;
    const int* mrow8 = mrow0 + 8 * SEQ;

    for (int k0 = 0; k0 < SEQ; k0 += 64) {
        __syncthreads();   // prior tile's PV done with Ks(P)/Vs

        // Load K,V tile (tf32-converted), natural layout, stride 72.
#pragma unroll
        for (int it = 0; it < 8; it++) {
            int id  = tid + it * 128;   // 0..1023
            int key = id >> 4;
            int d4  = id & 15;
            float4 kv = *(const float4*)(Kp + base + (size_t)(k0 + key) * DIM + d4 * 4);
            float4 vv = *(const float4*)(Vp + base + (size_t)(k0 + key) * DIM + d4 * 4);
            *(float4*)&Ks[key][d4 * 4] = make_float4(to_tf32(kv.x), to_tf32(kv.y),
                                                     to_tf32(kv.z), to_tf32(kv.w));
            *(float4*)&Vs[key][d4 * 4] = make_float4(to_tf32(vv.x), to_tf32(vv.y),
                                                     to_tf32(vv.z), to_tf32(vv.w));
        }
        __syncthreads();

        // ---- S = Q @ K^T : 8 n-blocks (8 keys each) x 8 k-steps ----
        float s[8][4];
#pragma unroll
        for (int kb = 0; kb < 8; kb++)
#pragma unroll
            for (int j = 0; j < 4; j++) s[kb][j] = 0.f;

#pragma unroll
        for (int ks = 0; ks < 8; ks++) {
            float b0[8], b1[8];
#pragma unroll
            for (int kb = 0; kb < 8; kb++) {
                b0[kb] = Ks[kb * 8 + r][ks * 8 + c];
                b1[kb] = Ks[kb * 8 + r][ks * 8 + c + 4];
            }
#pragma unroll
            for (int kb = 0; kb < 8; kb++)
                MMA_TF32(s[kb], aq[ks][0], aq[ks][1], aq[ks][2], aq[ks][3],
                         b0[kb], b1[kb]);
        }

        // ---- mask (1e-9 before softmax, faithful to reference) ----
#pragma unroll
        for (int kb = 0; kb < 8; kb++) {
            int2 m0 = *(const int2*)(mrow0 + k0 + kb * 8 + 2 * c);
            int2 m8 = *(const int2*)(mrow8 + k0 + kb * 8 + 2 * c);
            s[kb][0] = (m0.x == 0) ? 1e-9f : s[kb][0];
            s[kb][1] = (m0.y == 0) ? 1e-9f : s[kb][1];
            s[kb][2] = (m8.x == 0) ? 1e-9f : s[kb][2];
            s[kb][3] = (m8.y == 0) ? 1e-9f : s[kb][3];
        }

        // ---- online softmax (two row-halves per thread) ----
        float scale[2];
#pragma unroll
        for (int hh = 0; hh < 2; hh++) {
            float tm = -INFINITY;
#pragma unroll
            for (int kb = 0; kb < 8; kb++)
                tm = fmaxf(tm, fmaxf(s[kb][2 * hh], s[kb][2 * hh + 1]));
            tm = fmaxf(tm, __shfl_xor_sync(0xffffffffu, tm, 1));
            tm = fmaxf(tm, __shfl_xor_sync(0xffffffffu, tm, 2));
            float mn = fmaxf(mst[hh], tm);
            scale[hh] = __expf(mst[hh] - mn);
            float ps = 0.f;
#pragma unroll
            for (int kb = 0; kb < 8; kb++) {
                float p0 = __expf(s[kb][2 * hh]     - mn);
                float p1 = __expf(s[kb][2 * hh + 1] - mn);
                s[kb][2 * hh] = p0;
                s[kb][2 * hh + 1] = p1;
                ps += p0 + p1;
            }
            ps += __shfl_xor_sync(0xffffffffu, ps, 1);
            ps += __shfl_xor_sync(0xffffffffu, ps, 2);
            lst[hh] = lst[hh] * scale[hh] + ps;
            mst[hh] = mn;
        }

        // rescale O fragments
#pragma unroll
        for (int kb = 0; kb < 8; kb++) {
            ao[kb][0] *= scale[0];
            ao[kb][1] *= scale[0];
            ao[kb][2] *= scale[1];
            ao[kb][3] *= scale[1];
        }

        __syncthreads();   // all warps done reading Ks before P overwrite

        // Store P (tf32) into Ks region as P[qrow_local][key] (warp-local rows)
#pragma unroll
        for (int kb = 0; kb < 8; kb++) {
            *(float2*)&Ks[w * 16 + r][kb * 8 + 2 * c] =
                make_float2(to_tf32(s[kb][0]), to_tf32(s[kb][1]));
            *(float2*)&Ks[w * 16 + r + 8][kb * 8 + 2 * c] =
                make_float2(to_tf32(s[kb][2]), to_tf32(s[kb][3]));
        }
        __syncwarp();      // own warp's P visible (A-frags read own rows only)

        // ---- O += P @ V : k-steps over 8 key-octets, n-blocks over dk ----
#pragma unroll
        for (int ks = 0; ks < 8; ks++) {
            float a0 = Ks[w * 16 + r][ks * 8 + c];
            float a1 = Ks[w * 16 + r + 8][ks * 8 + c];
            float a2 = Ks[w * 16 + r][ks * 8 + c + 4];
            float a3 = Ks[w * 16 + r + 8][ks * 8 + c + 4];
#pragma unroll
            for (int kb = 0; kb < 8; kb++) {
                float b0 = Vs[ks * 8 + c][kb * 8 + r];
                float b1 = Vs[ks * 8 + c + 4][kb * 8 + r];
                MMA_TF32(ao[kb], a0, a1, a2, a3, b0, b1);
            }
        }
    }

    // Epilogue
    float inv0 = 1.f / lst[0];
    float inv1 = 1.f / lst[1];
    float* o0 = O + base + (size_t)qrow * DIM;
    float* o8 = o0 + 8 * DIM;
#pragma unroll
    for (int kb = 0; kb < 8; kb++) {
        *(float2*)(o0 + kb * 8 + 2 * c) = make_float2(ao[kb][0] * inv0, ao[kb][1] * inv0);
        *(float2*)(o8 + kb * 8 + 2 * c) = make_float2(ao[kb][2] * inv1, ao[kb][3] * inv1);
    }
}

// ---------------------------------------------------------------------------
// Launch
// ---------------------------------------------------------------------------
extern "C" void kernel_launch(void* const* d_in, const int* in_sizes, int n_in,
                              void* d_out, int out_size) {
    const float* Q    = (const float*)d_in[0];
    const float* K    = (const float*)d_in[1];
    const float* V    = (const float*)d_in[2];
    const int*   mask = (const int*)d_in[3];
    const float* Wq   = (const float*)d_in[4];
    const float* Wk   = (const float*)d_in[5];
    const float* Wv   = (const float*)d_in[6];
    const float* Wo   = (const float*)d_in[7];
    float* out = (float*)d_out;

    float *qp, *kp, *vp, *ao;
    cudaGetSymbolAddress((void**)&qp, g_qp);
    cudaGetSymbolAddress((void**)&kp, g_kp);
    cudaGetSymbolAddress((void**)&vp, g_vp);
    cudaGetSymbolAddress((void**)&ao, g_ao);

    dim3 gsz(DIM / 128, MTOT / 128);   // (8, 32)
    sgemm_tf32<<<gsz, 256>>>(Q, Wq, qp, MTOT, DIM, DIM);
    sgemm_tf32<<<gsz, 256>>>(K, Wk, kp, MTOT, DIM, DIM);
    sgemm_tf32<<<gsz, 256>>>(V, Wv, vp, MTOT, DIM, DIM);

    dim3 agrid(SEQ / 64, HEADS, BATCH);   // (32, 16, 2)
    attn_kernel<<<agrid, 128>>>(qp, kp, vp, mask, ao);

    sgemm_tf32<<<gsz, 256>>>(ao, Wo, out, MTOT, DIM, DIM);
}

// round 6
// speedup vs baseline: 1.8089x; 1.0131x over previous
#include <cuda_runtime.h>
#include <math.h>
#include <stdint.h>

// Problem constants
#define BATCH 2
#define SEQ   2048
#define DIM   1024
#define HEADS 16
#define DKH   64
#define MTOT  (BATCH * SEQ)   // 4096

// smem row strides (words). SK ≡ 4 (mod 32): QK-B / P accesses conflict-free.
// SV ≡ 8 (mod 32): PV-B accesses conflict-free.
#define SK 68
#define SV 72

// Scratch buffers (device globals — no allocation allowed)
__device__ float g_qp[MTOT * DIM];
__device__ float g_kp[MTOT * DIM];
__device__ float g_vp[MTOT * DIM];
__device__ float g_ao[MTOT * DIM];

// ---------------------------------------------------------------------------
// tf32 helpers
// ---------------------------------------------------------------------------
__device__ __forceinline__ float to_tf32(float x) {
    uint32_t u;
    asm("cvt.rna.tf32.f32 %0, %1;" : "=r"(u) : "f"(x));
    return __uint_as_float(u);
}

#define MMA_TF32(c, a0, a1, a2, a3, b0, b1)                                   \
    asm volatile(                                                             \
        "mma.sync.aligned.m16n8k8.row.col.f32.tf32.tf32.f32 "                 \
        "{%0,%1,%2,%3}, {%4,%5,%6,%7}, {%8,%9}, {%0,%1,%2,%3};"               \
        : "+f"((c)[0]), "+f"((c)[1]), "+f"((c)[2]), "+f"((c)[3])              \
        : "r"(__float_as_uint(a0)), "r"(__float_as_uint(a1)),                 \
          "r"(__float_as_uint(a2)), "r"(__float_as_uint(a3)),                 \
          "r"(__float_as_uint(b0)), "r"(__float_as_uint(b1)))

// ---------------------------------------------------------------------------
// tf32 tensor-core GEMM: C[M,N] = A[M,K] @ W[N,K]^T  (both row-major "NT")
// Block tile 128x128, BK=32, 256 threads = 8 warps (2x4), warp tile 64x32.
// ---------------------------------------------------------------------------
__global__ __launch_bounds__(256) void sgemm_tf32(const float* __restrict__ A,
                                                  const float* __restrict__ W,
                                                  float* __restrict__ C,
                                                  int M, int N, int K) {
    __shared__ float As[128][36];
    __shared__ float Bs[128][36];

    const int tid  = threadIdx.x;
    const int wid  = tid >> 5;
    const int lane = tid & 31;
    const int bm = blockIdx.y * 128;
    const int bn = blockIdx.x * 128;
    const int wm = (wid >> 2) * 64;
    const int wn = (wid & 3) * 32;
    const int lr = lane >> 2;
    const int lc = lane & 3;

    float acc[4][4][4];
#pragma unroll
    for (int i = 0; i < 4; i++)
#pragma unroll
        for (int j = 0; j < 4; j++)
#pragma unroll
            for (int r = 0; r < 4; r++) acc[i][j][r] = 0.f;

    for (int k0 = 0; k0 < K; k0 += 32) {
        float4 ra[4], rb[4];
#pragma unroll
        for (int it = 0; it < 4; it++) {
            int id  = tid + it * 256;
            int row = id >> 3;
            int seg = id & 7;
            ra[it] = *(const float4*)(A + (size_t)(bm + row) * K + k0 + seg * 4);
            rb[it] = *(const float4*)(W + (size_t)(bn + row) * K + k0 + seg * 4);
        }

        __syncthreads();

#pragma unroll
        for (int it = 0; it < 4; it++) {
            int id  = tid + it * 256;
            int row = id >> 3;
            int seg = id & 7;
            float va[4] = {ra[it].x, ra[it].y, ra[it].z, ra[it].w};
            float vb[4] = {rb[it].x, rb[it].y, rb[it].z, rb[it].w};
#pragma unroll
            for (int j = 0; j < 4; j++) {
                int k = seg * 4 + j;
                int c = k & 15;
                int col = (k & 16) + (c & 3) * 4 + (c >> 2);
                As[row][col] = to_tf32(va[j]);
                Bs[row][col] = to_tf32(vb[j]);
            }
        }
        __syncthreads();

#pragma unroll
        for (int blk = 0; blk < 2; blk++) {
            int kb = blk * 16;
            float4 alo[4], ahi[4], bf[4];
#pragma unroll
            for (int i = 0; i < 4; i++) {
                alo[i] = *(const float4*)&As[wm + i * 16 + lr][kb + lc * 4];
                ahi[i] = *(const float4*)&As[wm + i * 16 + 8 + lr][kb + lc * 4];
            }
#pragma unroll
            for (int j = 0; j < 4; j++)
                bf[j] = *(const float4*)&Bs[wn + j * 8 + lr][kb + lc * 4];
#pragma unroll
            for (int i = 0; i < 4; i++)
#pragma unroll
                for (int j = 0; j < 4; j++) {
                    MMA_TF32(acc[i][j], alo[i].x, ahi[i].x, alo[i].y, ahi[i].y,
                             bf[j].x, bf[j].y);
                    MMA_TF32(acc[i][j], alo[i].z, ahi[i].z, alo[i].w, ahi[i].w,
                             bf[j].z, bf[j].w);
                }
        }
    }

#pragma unroll
    for (int i = 0; i < 4; i++)
#pragma unroll
        for (int j = 0; j < 4; j++) {
            int row = bm + wm + i * 16 + lr;
            int col = bn + wn + j * 8 + lc * 2;
            *(float2*)&C[(size_t)row * N + col] =
                make_float2(acc[i][j][0], acc[i][j][1]);
            *(float2*)&C[(size_t)(row + 8) * N + col] =
                make_float2(acc[i][j][2], acc[i][j][3]);
        }
}

// ---------------------------------------------------------------------------
// Flash attention on tf32 tensor cores (conflict-free smem strides).
// Grid (SEQ/64, HEADS, BATCH), 128 threads = 4 warps; warp w owns q-rows
// [w*16, w*16+16).
// ---------------------------------------------------------------------------
__global__ __launch_bounds__(128) void attn_kernel(const float* __restrict__ Qp,
                                                   const float* __restrict__ Kp,
                                                   const float* __restrict__ Vp,
                                                   const int* __restrict__ mask,
                                                   float* __restrict__ O) {
    __shared__ float Ks[64 * SK];   // K tile (tf32) / later P tile [qrow][key]
    __shared__ float Vs[64 * SV];   // V tile (tf32) [key][dk]

    const int tid  = threadIdx.x;
    const int w    = tid >> 5;
    const int lane = tid & 31;
    const int r    = lane >> 2;    // 0..7
    const int c    = lane & 3;     // 0..3
    const int q0   = blockIdx.x * 64;
    const int h    = blockIdx.y;
    const int b    = blockIdx.z;

    const size_t base = (size_t)b * SEQ * DIM + (size_t)h * DKH;
    const int qrow = q0 + w * 16 + r;

    // Preload Q A-fragments for all 8 k-steps, scaled by 1/8.
    float aq[8][4];
    {
        const float* qr0 = Qp + base + (size_t)qrow * DIM;
        const float* qr8 = qr0 + 8 * DIM;
#pragma unroll
        for (int ks = 0; ks < 8; ks++) {
            aq[ks][0] = to_tf32(qr0[ks * 8 + c]     * 0.125f);
            aq[ks][1] = to_tf32(qr8[ks * 8 + c]     * 0.125f);
            aq[ks][2] = to_tf32(qr0[ks * 8 + c + 4] * 0.125f);
            aq[ks][3] = to_tf32(qr8[ks * 8 + c + 4] * 0.125f);
        }
    }

    float ao[8][4];
#pragma unroll
    for (int kb = 0; kb < 8; kb++)
#pragma unroll
        for (int j = 0; j < 4; j++) ao[kb][j] = 0.f;
    float mst[2] = {-INFINITY, -INFINITY};
    float lst[2] = {0.f, 0.f};

    const int* mrow0 = mask + (size_t)b * SEQ * SEQ + (size_t)qrow * SEQ;
    const int* mrow8 = mrow0 + 8 * SEQ;

    for (int k0 = 0; k0 < SEQ; k0 += 64) {
        __syncthreads();   // prior tile's PV done with Ks(P)/Vs

        // Load K,V tile (tf32-converted). K stride SK, V stride SV.
#pragma unroll
        for (int it = 0; it < 8; it++) {
            int id  = tid + it * 128;   // 0..1023
            int key = id >> 4;
            int d4  = id & 15;
            float4 kv = *(const float4*)(Kp + base + (size_t)(k0 + key) * DIM + d4 * 4);
            float4 vv = *(const float4*)(Vp + base + (size_t)(k0 + key) * DIM + d4 * 4);
            *(float4*)&Ks[key * SK + d4 * 4] = make_float4(to_tf32(kv.x), to_tf32(kv.y),
                                                           to_tf32(kv.z), to_tf32(kv.w));
            *(float4*)&Vs[key * SV + d4 * 4] = make_float4(to_tf32(vv.x), to_tf32(vv.y),
                                                           to_tf32(vv.z), to_tf32(vv.w));
        }
        __syncthreads();

        // ---- S = Q @ K^T ----
        float s[8][4];
#pragma unroll
        for (int kb = 0; kb < 8; kb++)
#pragma unroll
            for (int j = 0; j < 4; j++) s[kb][j] = 0.f;

#pragma unroll
        for (int ks = 0; ks < 8; ks++) {
            float b0[8], b1[8];
#pragma unroll
            for (int kb = 0; kb < 8; kb++) {
                b0[kb] = Ks[(kb * 8 + r) * SK + ks * 8 + c];
                b1[kb] = Ks[(kb * 8 + r) * SK + ks * 8 + c + 4];
            }
#pragma unroll
            for (int kb = 0; kb < 8; kb++)
                MMA_TF32(s[kb], aq[ks][0], aq[ks][1], aq[ks][2], aq[ks][3],
                         b0[kb], b1[kb]);
        }

        // ---- mask (1e-9 before softmax, faithful to reference) ----
#pragma unroll
        for (int kb = 0; kb < 8; kb++) {
            int2 m0 = *(const int2*)(mrow0 + k0 + kb * 8 + 2 * c);
            int2 m8 = *(const int2*)(mrow8 + k0 + kb * 8 + 2 * c);
            s[kb][0] = (m0.x == 0) ? 1e-9f : s[kb][0];
            s[kb][1] = (m0.y == 0) ? 1e-9f : s[kb][1];
            s[kb][2] = (m8.x == 0) ? 1e-9f : s[kb][2];
            s[kb][3] = (m8.y == 0) ? 1e-9f : s[kb][3];
        }

        // ---- online softmax ----
        float scale[2];
#pragma unroll
        for (int hh = 0; hh < 2; hh++) {
            float tm = -INFINITY;
#pragma unroll
            for (int kb = 0; kb < 8; kb++)
                tm = fmaxf(tm, fmaxf(s[kb][2 * hh], s[kb][2 * hh + 1]));
            tm = fmaxf(tm, __shfl_xor_sync(0xffffffffu, tm, 1));
            tm = fmaxf(tm, __shfl_xor_sync(0xffffffffu, tm, 2));
            float mn = fmaxf(mst[hh], tm);
            scale[hh] = __expf(mst[hh] - mn);
            float ps = 0.f;
#pragma unroll
            for (int kb = 0; kb < 8; kb++) {
                float p0 = __expf(s[kb][2 * hh]     - mn);
                float p1 = __expf(s[kb][2 * hh + 1] - mn);
                s[kb][2 * hh] = p0;
                s[kb][2 * hh + 1] = p1;
                ps += p0 + p1;
            }
            ps += __shfl_xor_sync(0xffffffffu, ps, 1);
            ps += __shfl_xor_sync(0xffffffffu, ps, 2);
            lst[hh] = lst[hh] * scale[hh] + ps;
            mst[hh] = mn;
        }

#pragma unroll
        for (int kb = 0; kb < 8; kb++) {
            ao[kb][0] *= scale[0];
            ao[kb][1] *= scale[0];
            ao[kb][2] *= scale[1];
            ao[kb][3] *= scale[1];
        }

        __syncthreads();   // all warps done reading Ks before P overwrite

        // Store P (tf32) into Ks region as P[qrow_local][key]
#pragma unroll
        for (int kb = 0; kb < 8; kb++) {
            *(float2*)&Ks[(w * 16 + r) * SK + kb * 8 + 2 * c] =
                make_float2(to_tf32(s[kb][0]), to_tf32(s[kb][1]));
            *(float2*)&Ks[(w * 16 + r + 8) * SK + kb * 8 + 2 * c] =
                make_float2(to_tf32(s[kb][2]), to_tf32(s[kb][3]));
        }
        __syncwarp();      // own warp's P visible (A-frags read own rows only)

        // ---- O += P @ V ----
#pragma unroll
        for (int ks = 0; ks < 8; ks++) {
            float a0 = Ks[(w * 16 + r) * SK + ks * 8 + c];
            float a1 = Ks[(w * 16 + r + 8) * SK + ks * 8 + c];
            float a2 = Ks[(w * 16 + r) * SK + ks * 8 + c + 4];
            float a3 = Ks[(w * 16 + r + 8) * SK + ks * 8 + c + 4];
#pragma unroll
            for (int kb = 0; kb < 8; kb++) {
                float b0 = Vs[(ks * 8 + c) * SV + kb * 8 + r];
                float b1 = Vs[(ks * 8 + c + 4) * SV + kb * 8 + r];
                MMA_TF32(ao[kb], a0, a1, a2, a3, b0, b1);
            }
        }
    }

    // Epilogue
    float inv0 = 1.f / lst[0];
    float inv1 = 1.f / lst[1];
    float* o0 = O + base + (size_t)qrow * DIM;
    float* o8 = o0 + 8 * DIM;
#pragma unroll
    for (int kb = 0; kb < 8; kb++) {
        *(float2*)(o0 + kb * 8 + 2 * c) = make_float2(ao[kb][0] * inv0, ao[kb][1] * inv0);
        *(float2*)(o8 + kb * 8 + 2 * c) = make_float2(ao[kb][2] * inv1, ao[kb][3] * inv1);
    }
}

// ---------------------------------------------------------------------------
// Launch
// ---------------------------------------------------------------------------
extern "C" void kernel_launch(void* const* d_in, const int* in_sizes, int n_in,
                              void* d_out, int out_size) {
    const float* Q    = (const float*)d_in[0];
    const float* K    = (const float*)d_in[1];
    const float* V    = (const float*)d_in[2];
    const int*   mask = (const int*)d_in[3];
    const float* Wq   = (const float*)d_in[4];
    const float* Wk   = (const float*)d_in[5];
    const float* Wv   = (const float*)d_in[6];
    const float* Wo   = (const float*)d_in[7];
    float* out = (float*)d_out;

    float *qp, *kp, *vp, *ao;
    cudaGetSymbolAddress((void**)&qp, g_qp);
    cudaGetSymbolAddress((void**)&kp, g_kp);
    cudaGetSymbolAddress((void**)&vp, g_vp);
    cudaGetSymbolAddress((void**)&ao, g_ao);

    dim3 gsz(DIM / 128, MTOT / 128);   // (8, 32)
    sgemm_tf32<<<gsz, 256>>>(Q, Wq, qp, MTOT, DIM, DIM);
    sgemm_tf32<<<gsz, 256>>>(K, Wk, kp, MTOT, DIM, DIM);
    sgemm_tf32<<<gsz, 256>>>(V, Wv, vp, MTOT, DIM, DIM);

    dim3 agrid(SEQ / 64, HEADS, BATCH);   // (32, 16, 2)
    attn_kernel<<<agrid, 128>>>(qp, kp, vp, mask, ao);

    sgemm_tf32<<<gsz, 256>>>(ao, Wo, out, MTOT, DIM, DIM);
}